// round 5
// baseline (speedup 1.0000x reference)
#include <cuda_runtime.h>
#include <cuda_fp16.h>
#include <cstdint>

// out[bn] = A @ x[bn]^T @ B, fused, mma.sync fp16/f32acc, cp.async 4-stage pipeline.
// G1: T[a=64, p=224pad] = sum_c A[a,c] x[p,c]  (K=768, 24 chunks of 32, X kept f32 in SMEM)
// G2: out[a,h] = sum_p T[a,p] B[p,h]           (K=224)
#define P_DIM 196
#define C_DIM 768
#define NCH 24
#define PP 224
#define NST 4
#define STAGE_B (PP * 128)            // 28672 B per stage (f32, swizzled, k-permuted)
#define OFF_A 0
#define A_BYTES (64 * 1536)           // 98304 (f16, swizzled)
#define OFF_X A_BYTES                 // 98304
#define OFF_T OFF_X                   // T aliases stages 0-1 after G1
#define T_PITCH 464                   // bytes per T row (232 halves, conflict-free)
#define OFF_B2 (OFF_X + 32768)        // Bs aliases stage region after T
#define SMEM_TOTAL (OFF_X + NST * STAGE_B)   // 212992

#define DEVINL __device__ __forceinline__

DEVINL uint32_t smem_u32(const void* p) {
    uint32_t a;
    asm("{ .reg .u64 t; cvta.to.shared.u64 t, %1; cvt.u32.u64 %0, t; }" : "=r"(a) : "l"(p));
    return a;
}
DEVINL uint32_t f2h2(float lo, float hi) {
    __half2 h = __floats2half2_rn(lo, hi);
    return *reinterpret_cast<uint32_t*>(&h);
}
DEVINL void ldsm4(uint32_t* r, uint32_t addr) {
    asm volatile("ldmatrix.sync.aligned.m8n8.x4.shared.b16 {%0,%1,%2,%3}, [%4];"
                 : "=r"(r[0]), "=r"(r[1]), "=r"(r[2]), "=r"(r[3]) : "r"(addr));
}
DEVINL void lds128f(float& f0, float& f1, float& f2, float& f3, uint32_t addr) {
    asm volatile("ld.shared.v4.f32 {%0,%1,%2,%3}, [%4];"
                 : "=f"(f0), "=f"(f1), "=f"(f2), "=f"(f3) : "r"(addr));
}
DEVINL void mma16816(float* d, const uint32_t* a, const uint32_t* b) {
    asm volatile("mma.sync.aligned.m16n8k16.row.col.f32.f16.f16.f32 "
                 "{%0,%1,%2,%3}, {%4,%5,%6,%7}, {%8,%9}, {%0,%1,%2,%3};"
                 : "+f"(d[0]), "+f"(d[1]), "+f"(d[2]), "+f"(d[3])
                 : "r"(a[0]), "r"(a[1]), "r"(a[2]), "r"(a[3]), "r"(b[0]), "r"(b[1]));
}

// Issue one X chunk (32 f32 per row, rows 0..195) as 8-byte cp.asyncs with
// k-permutation (stored 8B-unit u' <- logical k pair (u'&1)*8 + (u'>>1)*2) and
// XOR-(p&7) swizzle on the 16B chunk index.
DEVINL void issue_chunk(uint32_t sb, const float* __restrict__ xb, int ch, int tid) {
    const float* src0 = xb + ch * 32;
    const uint32_t stg = sb + OFF_X + (ch & 3) * STAGE_B;
    for (int i = tid; i < P_DIM * 16; i += 256) {
        int p = i >> 4, u = i & 15;
        int up = u & 7;
        int k = ((u >> 3) << 4) + ((up & 1) << 3) + ((up >> 1) << 1);
        uint32_t dst = stg + p * 128 + ((((u >> 1) ^ (p & 7)) << 4)) + ((u & 1) << 3);
        const float* s = src0 + p * C_DIM + k;
        asm volatile("cp.async.ca.shared.global [%0], [%1], 8;" :: "r"(dst), "l"(s));
    }
    asm volatile("cp.async.commit_group;" ::: "memory");
}

__global__ void __launch_bounds__(256, 1) sepnet_fused_kernel(
    const float* __restrict__ x, const float* __restrict__ Amat,
    const float* __restrict__ Bmat, float* __restrict__ out)
{
    extern __shared__ char smem[];
    const uint32_t sb = smem_u32(smem);
    const int tid = threadIdx.x;
    const int wid = tid >> 5;
    const int lane = tid & 31;
    const int bn = blockIdx.x;
    const float* xb = x + (size_t)bn * (P_DIM * C_DIM);

    // prologue: get DRAM going immediately (3 stages in flight)
    issue_chunk(sb, xb, 0, tid);
    issue_chunk(sb, xb, 1, tid);
    issue_chunk(sb, xb, 2, tid);

    // A -> f16 SMEM, swizzled, once per CTA (hot in L2 after wave 1)
    {
        const int row = tid >> 2;                 // 4 threads per row
#pragma unroll 4
        for (int j = 0; j < 48; j++) {
            int k4 = (tid & 3) + j * 4;           // float4 index, k = 4*k4
            float4 v = *reinterpret_cast<const float4*>(Amat + row * C_DIM + k4 * 4);
            uint32_t off = k4 * 8;                // byte offset of 4 halves
            uint32_t dst = sb + OFF_A + row * 1536 + (off & ~127u) +
                           ((((off >> 4) & 7) ^ (row & 7)) << 4) + (off & 8);
            uint32_t h01 = f2h2(v.x, v.y), h23 = f2h2(v.z, v.w);
            asm volatile("st.shared.v2.b32 [%0], {%1, %2};" :: "r"(dst), "r"(h01), "r"(h23) : "memory");
        }
    }
    // zero X pad rows (196..223) in every stage (cp.async never touches them)
#pragma unroll
    for (int s = 0; s < NST; s++) {
        for (int i = tid; i < 28 * 32; i += 256) {
            uint32_t a = sb + OFF_X + s * STAGE_B + (P_DIM + (i >> 5)) * 128 + (i & 31) * 4;
            asm volatile("st.shared.b32 [%0], %1;" :: "r"(a), "r"(0u) : "memory");
        }
    }

    // ---- G1: warp = (agrp: 32 a-rows) x (pq: 56 p-cols) ----
    float acc[2][7][4];
#pragma unroll
    for (int i = 0; i < 2; i++)
#pragma unroll
        for (int t = 0; t < 7; t++)
            acc[i][t][0] = acc[i][t][1] = acc[i][t][2] = acc[i][t][3] = 0.0f;

    const int agrp = wid >> 2, pq = wid & 3;
    const int pbase = pq * 56;
    const int arow0 = agrp * 32 + (lane & 15);
    const int arow7 = arow0 & 7;
    const int acol = (lane & 16) ? 8 : 0;
    const int brow = lane >> 2, bq = lane & 3;
    const int bp0 = pbase + brow;                 // (bp0 & 7) == brow

    __syncthreads();

    for (int ch = 0; ch < NCH; ch++) {
        asm volatile("cp.async.wait_group 2;" ::: "memory");
        __syncthreads();
        if (ch + 3 < NCH) issue_chunk(sb, xb, ch + 3, tid);
        else asm volatile("cp.async.commit_group;" ::: "memory");  // empty group keeps count

        const uint32_t stg = sb + OFF_X + (ch & 3) * STAGE_B;
#pragma unroll
        for (int ks = 0; ks < 2; ks++) {
            uint32_t a0[4], a1[4];
            {
                uint32_t off = (uint32_t)(ch * 32 + ks * 16 + acol) * 2;
                uint32_t blk = off & ~127u;
                uint32_t c = (off >> 4) & 7;
                ldsm4(a0, sb + OFF_A + arow0 * 1536 + blk + ((c ^ arow7) << 4));
                ldsm4(a1, sb + OFF_A + (arow0 + 16) * 1536 + blk + ((c ^ ((arow0 + 16) & 7)) << 4));
            }
            const uint32_t cc = (uint32_t)((ks * 4 + bq) ^ brow) << 4;
#pragma unroll
            for (int t = 0; t < 7; t++) {
                float f0, f1, f2, f3;
                lds128f(f0, f1, f2, f3, stg + (bp0 + t * 8) * 128 + cc);
                uint32_t b[2];
                b[0] = f2h2(f0, f1);
                b[1] = f2h2(f2, f3);
                mma16816(acc[0][t], a0, b);
                mma16816(acc[1][t], a1, b);
            }
        }
    }

    // ---- T (f16) into stage region, pitch 464 B ----
#pragma unroll
    for (int i = 0; i < 2; i++)
#pragma unroll
        for (int t = 0; t < 7; t++) {
            int r = agrp * 32 + i * 16 + (lane >> 2);
            int c = pbase + t * 8 + (lane & 3) * 2;
            asm volatile("st.shared.b32 [%0], %1;"
                :: "r"(sb + OFF_T + r * T_PITCH + c * 2), "r"(f2h2(acc[i][t][0], acc[i][t][1])) : "memory");
            asm volatile("st.shared.b32 [%0], %1;"
                :: "r"(sb + OFF_T + (r + 8) * T_PITCH + c * 2), "r"(f2h2(acc[i][t][2], acc[i][t][3])) : "memory");
        }
    // Bs[h][p] f16, pitch 464 B, pads zero  (region disjoint from T and live stages)
    for (int i = tid; i < 64 * PP; i += 256) {
        int p = i >> 6, h = i & 63;
        float v = (p < P_DIM) ? Bmat[p * 64 + h] : 0.0f;
        unsigned short hb = __half_as_ushort(__float2half_rn(v));
        asm volatile("st.shared.b16 [%0], %1;" :: "r"(sb + OFF_B2 + h * T_PITCH + p * 2), "h"(hb) : "memory");
    }
    __syncthreads();

    // ---- G2: out[a,h] = sum_p T[a,p] Bs[h,p], K = 224 ----
    float o[4][4];
#pragma unroll
    for (int i = 0; i < 4; i++)
        o[i][0] = o[i][1] = o[i][2] = o[i][3] = 0.0f;
    const int a2row = (wid >> 1) * 16 + (lane & 15);
    const int a2co = (lane & 16) ? 8 : 0;
    const int hh = (wid & 1) * 32;
    const int browofs = (lane & 7) + ((lane & 16) >> 1);
    const int bcolofs = ((lane >> 3) & 1) * 8;
#pragma unroll
    for (int ks = 0; ks < 14; ks++) {
        const int k0 = ks * 16;
        uint32_t a[4];
        ldsm4(a, sb + OFF_T + a2row * T_PITCH + (k0 + a2co) * 2);
#pragma unroll
        for (int g = 0; g < 2; g++) {
            uint32_t b[4];
            ldsm4(b, sb + OFF_B2 + (hh + g * 16 + browofs) * T_PITCH + (k0 + bcolofs) * 2);
            mma16816(o[2 * g], a, &b[0]);
            mma16816(o[2 * g + 1], a, &b[2]);
        }
    }
    {
        float* ob = out + (size_t)bn * 4096;
        const int r0 = (wid >> 1) * 16 + lane / 4;
        const int cb = hh + (lane & 3) * 2;
#pragma unroll
        for (int nt = 0; nt < 4; nt++) {
            int c = cb + nt * 8;
            *reinterpret_cast<float2*>(ob + r0 * 64 + c) = make_float2(o[nt][0], o[nt][1]);
            *reinterpret_cast<float2*>(ob + (r0 + 8) * 64 + c) = make_float2(o[nt][2], o[nt][3]);
        }
    }
}

extern "C" void kernel_launch(void* const* d_in, const int* in_sizes, int n_in,
                              void* d_out, int out_size) {
    int ix = 0, ia = 1, ib = 2;
    for (int i = 0; i < n_in; i++) {
        if (in_sizes[i] == 237244416) ix = i;
        else if (in_sizes[i] == 49152) ia = i;
        else if (in_sizes[i] == 12544) ib = i;
    }
    const float* x = (const float*)d_in[ix];
    const float* A = (const float*)d_in[ia];
    const float* B = (const float*)d_in[ib];
    float* out = (float*)d_out;

    cudaFuncSetAttribute(sepnet_fused_kernel,
                         cudaFuncAttributeMaxDynamicSharedMemorySize, SMEM_TOTAL);
    sepnet_fused_kernel<<<1576, 256, SMEM_TOTAL>>>(x, A, B, out);
}

// round 6
// speedup vs baseline: 1.9700x; 1.9700x over previous
#include <cuda_runtime.h>
#include <cuda_fp16.h>
#include <cstdint>

// out[bn] = A @ x[bn]^T @ B, fused, legacy mma.sync (fp16 in / f32 acc).
// R6 = R4 (proven correct, 334us) + 2 CTAs/SM occupancy (launch_bounds(256,2)).
// G1: T[a=64, p=208pad] = sum_c A[a,c] x[p,c]   (K=768, 24 chunks of 32)
// G2: out[a,h] = sum_p T[a,p] B[p,h]            (K=208, pad zero)
#define P_DIM 196
#define C_DIM 768
#define KC 32
#define NCH (C_DIM / KC)          // 24
#define PP 208                    // padded p
#define XPITCH 40                 // halves per row (80 B, 16B-aligned rows)
#define TPITCH 216                // halves per row (432 B)

#define ABUF_BYTES (64 * XPITCH * 2)    // 5120
#define XBUF_BYTES (PP * XPITCH * 2)    // 16640
#define OFF_AS 0
#define OFF_XS (2 * ABUF_BYTES)                  // 10240
#define OFF_TS (OFF_XS + 2 * XBUF_BYTES)         // 43520
#define OFF_BS (OFF_TS + 64 * TPITCH * 2)        // 71168
#define SMEM_BYTES (OFF_BS + 64 * TPITCH * 2)    // 98816

#define DEVINL __device__ __forceinline__

DEVINL uint32_t smem_u32(const void* p) {
    uint32_t a;
    asm("{ .reg .u64 t; cvta.to.shared.u64 t, %1; cvt.u32.u64 %0, t; }" : "=r"(a) : "l"(p));
    return a;
}

DEVINL uint32_t f2h2(float lo, float hi) {
    __half2 h = __floats2half2_rn(lo, hi);
    return *reinterpret_cast<uint32_t*>(&h);
}

DEVINL void ldsm4(uint32_t* r, uint32_t addr) {
    asm volatile("ldmatrix.sync.aligned.m8n8.x4.shared.b16 {%0,%1,%2,%3}, [%4];"
                 : "=r"(r[0]), "=r"(r[1]), "=r"(r[2]), "=r"(r[3]) : "r"(addr));
}
DEVINL void ldsm2(uint32_t* r, uint32_t addr) {
    asm volatile("ldmatrix.sync.aligned.m8n8.x2.shared.b16 {%0,%1}, [%2];"
                 : "=r"(r[0]), "=r"(r[1]) : "r"(addr));
}
DEVINL void mma16816(float* d, const uint32_t* a, const uint32_t* b) {
    asm volatile("mma.sync.aligned.m16n8k16.row.col.f32.f16.f16.f32 "
                 "{%0,%1,%2,%3}, {%4,%5,%6,%7}, {%8,%9}, {%0,%1,%2,%3};"
                 : "+f"(d[0]), "+f"(d[1]), "+f"(d[2]), "+f"(d[3])
                 : "r"(a[0]), "r"(a[1]), "r"(a[2]), "r"(a[3]), "r"(b[0]), "r"(b[1]));
}

__global__ void __launch_bounds__(256, 2) sepnet_fused_kernel(
    const float* __restrict__ x, const float* __restrict__ Amat,
    const float* __restrict__ Bmat, float* __restrict__ out)
{
    extern __shared__ char smem[];
    const uint32_t sb = smem_u32(smem);
    const int tid = threadIdx.x;
    const int wid = tid >> 5;
    const int lane = tid & 31;
    const int bn = blockIdx.x;
    const float* xb = x + (size_t)bn * (P_DIM * C_DIM);

    // ---- one-time setup: Bs[h][p] (f16, transposed, pad p>=196 zero) ----
    for (int idx = tid; idx < 64 * PP; idx += 256) {
        int p = idx >> 6, h = idx & 63;
        float v = (p < P_DIM) ? Bmat[p * 64 + h] : 0.0f;
        *reinterpret_cast<__half*>(smem + OFF_BS + (h * TPITCH + p) * 2) = __float2half_rn(v);
    }
    // zero Xs pad rows (196..207) in both buffers: 2 * 12 rows * 80 B = 1920 B
    for (int idx = tid; idx < 480; idx += 256) {
        int buf = idx / 240, o = idx % 240;
        *reinterpret_cast<uint32_t*>(smem + OFF_XS + buf * XBUF_BYTES + P_DIM * 80 + o * 4) = 0u;
    }

    // ---- G1 accumulators: warp (wid>>1) owns a-rows, (wid&1) owns p-half ----
    float acc[13][4];
#pragma unroll
    for (int i = 0; i < 13; i++) {
        acc[i][0] = acc[i][1] = acc[i][2] = acc[i][3] = 0.0f;
    }

    const int arow = (wid >> 1) * 16 + (lane & 15);     // A-frag row
    const int acolofs = (lane & 16) ? 8 : 0;            // A-frag col offset
    const int phalf = (wid & 1) * 104;                  // p-half base
    const int browofs = (lane & 7) + ((lane & 16) >> 1);// B-frag row offset (x4)
    const int bcolofs = ((lane >> 3) & 1) * 8;          // B-frag col offset (x4)

    float4 xr[7], ar[2];

    // prologue loads (chunk 0)
#pragma unroll
    for (int i = 0; i < 6; i++) {
        int idx = i * 256 + tid, row = idx >> 3, c4 = idx & 7;
        xr[i] = *reinterpret_cast<const float4*>(xb + row * C_DIM + c4 * 4);
    }
    if (tid < 32) {
        int idx = 1536 + tid, row = idx >> 3, c4 = idx & 7;
        xr[6] = *reinterpret_cast<const float4*>(xb + row * C_DIM + c4 * 4);
    }
#pragma unroll
    for (int i = 0; i < 2; i++) {
        int idx = i * 256 + tid, row = idx >> 3, c4 = idx & 7;
        ar[i] = *reinterpret_cast<const float4*>(Amat + row * C_DIM + c4 * 4);
    }

    for (int ch = 0; ch < NCH; ch++) {
        const int buf = ch & 1;
        // ---- cvt + STS staged regs into buf (4 halves = 8 bytes per float4) ----
        {
            char* xsb = smem + OFF_XS + buf * XBUF_BYTES;
#pragma unroll
            for (int i = 0; i < 6; i++) {
                int idx = i * 256 + tid, row = idx >> 3, c4 = idx & 7;
                uint32_t* d = reinterpret_cast<uint32_t*>(xsb + row * 80 + c4 * 8);
                d[0] = f2h2(xr[i].x, xr[i].y);
                d[1] = f2h2(xr[i].z, xr[i].w);
            }
            if (tid < 32) {
                int idx = 1536 + tid, row = idx >> 3, c4 = idx & 7;
                uint32_t* d = reinterpret_cast<uint32_t*>(xsb + row * 80 + c4 * 8);
                d[0] = f2h2(xr[6].x, xr[6].y);
                d[1] = f2h2(xr[6].z, xr[6].w);
            }
            char* asb = smem + OFF_AS + buf * ABUF_BYTES;
#pragma unroll
            for (int i = 0; i < 2; i++) {
                int idx = i * 256 + tid, row = idx >> 3, c4 = idx & 7;
                uint32_t* d = reinterpret_cast<uint32_t*>(asb + row * 80 + c4 * 8);
                d[0] = f2h2(ar[i].x, ar[i].y);
                d[1] = f2h2(ar[i].z, ar[i].w);
            }
        }
        __syncthreads();

        // ---- issue next chunk's LDGs (latency hides under mma below) ----
        if (ch + 1 < NCH) {
            const float* xc = xb + (ch + 1) * KC;
            const float* ac = Amat + (ch + 1) * KC;
#pragma unroll
            for (int i = 0; i < 6; i++) {
                int idx = i * 256 + tid, row = idx >> 3, c4 = idx & 7;
                xr[i] = *reinterpret_cast<const float4*>(xc + row * C_DIM + c4 * 4);
            }
            if (tid < 32) {
                int idx = 1536 + tid, row = idx >> 3, c4 = idx & 7;
                xr[6] = *reinterpret_cast<const float4*>(xc + row * C_DIM + c4 * 4);
            }
#pragma unroll
            for (int i = 0; i < 2; i++) {
                int idx = i * 256 + tid, row = idx >> 3, c4 = idx & 7;
                ar[i] = *reinterpret_cast<const float4*>(ac + row * C_DIM + c4 * 4);
            }
        }

        // ---- mma over buf ----
        {
            const uint32_t asb = sb + OFF_AS + buf * ABUF_BYTES;
            const uint32_t xsb = sb + OFF_XS + buf * XBUF_BYTES;
#pragma unroll
            for (int ks = 0; ks < 2; ks++) {
                const int k0 = ks * 16;
                uint32_t a[4];
                ldsm4(a, asb + (arow * XPITCH + k0 + acolofs) * 2);
#pragma unroll
                for (int g = 0; g < 6; g++) {
                    uint32_t b[4];
                    ldsm4(b, xsb + ((phalf + g * 16 + browofs) * XPITCH + k0 + bcolofs) * 2);
                    mma16816(acc[2 * g], a, &b[0]);
                    mma16816(acc[2 * g + 1], a, &b[2]);
                }
                uint32_t b2[2];
                ldsm2(b2, xsb + ((phalf + 96 + (lane & 7)) * XPITCH + k0 + ((lane & 8) ? 8 : 0)) * 2);
                mma16816(acc[12], a, b2);
            }
        }
        __syncthreads();
    }

    // ---- store T (f16) to SMEM [a][p] ----
    {
        char* ts = smem + OFF_TS;
        const int r0 = (wid >> 1) * 16 + lane / 4;
        const int cb = phalf + (lane & 3) * 2;
#pragma unroll
        for (int nt = 0; nt < 13; nt++) {
            int c = cb + nt * 8;
            *reinterpret_cast<uint32_t*>(ts + (r0 * TPITCH + c) * 2) = f2h2(acc[nt][0], acc[nt][1]);
            *reinterpret_cast<uint32_t*>(ts + ((r0 + 8) * TPITCH + c) * 2) = f2h2(acc[nt][2], acc[nt][3]);
        }
    }
    __syncthreads();

    // ---- G2: out[a,h] = sum_p T[a,p] B[p,h], K = 208 ----
    float o[4][4];
#pragma unroll
    for (int i = 0; i < 4; i++) {
        o[i][0] = o[i][1] = o[i][2] = o[i][3] = 0.0f;
    }
    const uint32_t tsb = sb + OFF_TS;
    const uint32_t bsb = sb + OFF_BS;
    const int a2row = (wid >> 1) * 16 + (lane & 15);
    const int a2co = (lane & 16) ? 8 : 0;
    const int hhalf = (wid & 1) * 32;
#pragma unroll
    for (int ks = 0; ks < 13; ks++) {
        const int k0 = ks * 16;
        uint32_t a[4];
        ldsm4(a, tsb + (a2row * TPITCH + k0 + a2co) * 2);
#pragma unroll
        for (int g = 0; g < 2; g++) {
            uint32_t b[4];
            ldsm4(b, bsb + ((hhalf + g * 16 + browofs) * TPITCH + k0 + bcolofs) * 2);
            mma16816(o[2 * g], a, &b[0]);
            mma16816(o[2 * g + 1], a, &b[2]);
        }
    }

    // ---- epilogue ----
    {
        float* ob = out + (size_t)bn * 4096;
        const int r0 = (wid >> 1) * 16 + lane / 4;
        const int cb = hhalf + (lane & 3) * 2;
#pragma unroll
        for (int nt = 0; nt < 4; nt++) {
            int c = cb + nt * 8;
            *reinterpret_cast<float2*>(ob + r0 * 64 + c) = make_float2(o[nt][0], o[nt][1]);
            *reinterpret_cast<float2*>(ob + (r0 + 8) * 64 + c) = make_float2(o[nt][2], o[nt][3]);
        }
    }
}

extern "C" void kernel_launch(void* const* d_in, const int* in_sizes, int n_in,
                              void* d_out, int out_size) {
    int ix = 0, ia = 1, ib = 2;
    for (int i = 0; i < n_in; i++) {
        if (in_sizes[i] == 237244416) ix = i;
        else if (in_sizes[i] == 49152) ia = i;
        else if (in_sizes[i] == 12544) ib = i;
    }
    const float* x = (const float*)d_in[ix];
    const float* A = (const float*)d_in[ia];
    const float* B = (const float*)d_in[ib];
    float* out = (float*)d_out;

    cudaFuncSetAttribute(sepnet_fused_kernel,
                         cudaFuncAttributeMaxDynamicSharedMemorySize, SMEM_BYTES);
    sepnet_fused_kernel<<<1576, 256, SMEM_BYTES>>>(x, A, B, out);
}

// round 7
// speedup vs baseline: 2.1129x; 1.0725x over previous
#include <cuda_runtime.h>
#include <cuda_fp16.h>
#include <cstdint>

// out[bn] = A @ x[bn]^T @ B, fused, legacy mma.sync (fp16 in / f32 acc).
// R7 = R6 (246us) + LDG hoist above barrier + single sync per chunk.
// G1: T[a=64, p=208pad] = sum_c A[a,c] x[p,c]   (K=768, 24 chunks of 32)
// G2: out[a,h] = sum_p T[a,p] B[p,h]            (K=208, pad zero)
#define P_DIM 196
#define C_DIM 768
#define KC 32
#define NCH (C_DIM / KC)          // 24
#define PP 208                    // padded p
#define XPITCH 40                 // halves per row (80 B, 16B-aligned rows)
#define TPITCH 216                // halves per row (432 B)

#define ABUF_BYTES (64 * XPITCH * 2)    // 5120
#define XBUF_BYTES (PP * XPITCH * 2)    // 16640
#define OFF_AS 0
#define OFF_XS (2 * ABUF_BYTES)                  // 10240
#define OFF_TS (OFF_XS + 2 * XBUF_BYTES)         // 43520
#define OFF_BS (OFF_TS + 64 * TPITCH * 2)        // 71168
#define SMEM_BYTES (OFF_BS + 64 * TPITCH * 2)    // 98816

#define DEVINL __device__ __forceinline__

DEVINL uint32_t smem_u32(const void* p) {
    uint32_t a;
    asm("{ .reg .u64 t; cvta.to.shared.u64 t, %1; cvt.u32.u64 %0, t; }" : "=r"(a) : "l"(p));
    return a;
}

DEVINL uint32_t f2h2(float lo, float hi) {
    __half2 h = __floats2half2_rn(lo, hi);
    return *reinterpret_cast<uint32_t*>(&h);
}

DEVINL void ldsm4(uint32_t* r, uint32_t addr) {
    asm volatile("ldmatrix.sync.aligned.m8n8.x4.shared.b16 {%0,%1,%2,%3}, [%4];"
                 : "=r"(r[0]), "=r"(r[1]), "=r"(r[2]), "=r"(r[3]) : "r"(addr));
}
DEVINL void ldsm2(uint32_t* r, uint32_t addr) {
    asm volatile("ldmatrix.sync.aligned.m8n8.x2.shared.b16 {%0,%1}, [%2];"
                 : "=r"(r[0]), "=r"(r[1]) : "r"(addr));
}
DEVINL void mma16816(float* d, const uint32_t* a, const uint32_t* b) {
    asm volatile("mma.sync.aligned.m16n8k16.row.col.f32.f16.f16.f32 "
                 "{%0,%1,%2,%3}, {%4,%5,%6,%7}, {%8,%9}, {%0,%1,%2,%3};"
                 : "+f"(d[0]), "+f"(d[1]), "+f"(d[2]), "+f"(d[3])
                 : "r"(a[0]), "r"(a[1]), "r"(a[2]), "r"(a[3]), "r"(b[0]), "r"(b[1]));
}

__global__ void __launch_bounds__(256, 2) sepnet_fused_kernel(
    const float* __restrict__ x, const float* __restrict__ Amat,
    const float* __restrict__ Bmat, float* __restrict__ out)
{
    extern __shared__ char smem[];
    const uint32_t sb = smem_u32(smem);
    const int tid = threadIdx.x;
    const int wid = tid >> 5;
    const int lane = tid & 31;
    const int bn = blockIdx.x;
    const float* xb = x + (size_t)bn * (P_DIM * C_DIM);

    // ---- one-time setup: Bs[h][p] (f16, transposed, pad p>=196 zero) ----
    for (int idx = tid; idx < 64 * PP; idx += 256) {
        int p = idx >> 6, h = idx & 63;
        float v = (p < P_DIM) ? Bmat[p * 64 + h] : 0.0f;
        *reinterpret_cast<__half*>(smem + OFF_BS + (h * TPITCH + p) * 2) = __float2half_rn(v);
    }
    // zero Xs pad rows (196..207) in both buffers
    for (int idx = tid; idx < 480; idx += 256) {
        int buf = idx / 240, o = idx % 240;
        *reinterpret_cast<uint32_t*>(smem + OFF_XS + buf * XBUF_BYTES + P_DIM * 80 + o * 4) = 0u;
    }

    // ---- G1 accumulators ----
    float acc[13][4];
#pragma unroll
    for (int i = 0; i < 13; i++) {
        acc[i][0] = acc[i][1] = acc[i][2] = acc[i][3] = 0.0f;
    }

    const int arow = (wid >> 1) * 16 + (lane & 15);
    const int acolofs = (lane & 16) ? 8 : 0;
    const int phalf = (wid & 1) * 104;
    const int browofs = (lane & 7) + ((lane & 16) >> 1);
    const int bcolofs = ((lane >> 3) & 1) * 8;

    float4 xr[7], ar[2];

    // prologue loads (chunk 0)
#pragma unroll
    for (int i = 0; i < 6; i++) {
        int idx = i * 256 + tid, row = idx >> 3, c4 = idx & 7;
        xr[i] = *reinterpret_cast<const float4*>(xb + row * C_DIM + c4 * 4);
    }
    if (tid < 32) {
        int idx = 1536 + tid, row = idx >> 3, c4 = idx & 7;
        xr[6] = *reinterpret_cast<const float4*>(xb + row * C_DIM + c4 * 4);
    }
#pragma unroll
    for (int i = 0; i < 2; i++) {
        int idx = i * 256 + tid, row = idx >> 3, c4 = idx & 7;
        ar[i] = *reinterpret_cast<const float4*>(Amat + row * C_DIM + c4 * 4);
    }

    for (int ch = 0; ch < NCH; ch++) {
        const int buf = ch & 1;
        // ---- cvt + STS staged regs into buf ----
        {
            char* xsb = smem + OFF_XS + buf * XBUF_BYTES;
#pragma unroll
            for (int i = 0; i < 6; i++) {
                int idx = i * 256 + tid, row = idx >> 3, c4 = idx & 7;
                uint32_t* d = reinterpret_cast<uint32_t*>(xsb + row * 80 + c4 * 8);
                d[0] = f2h2(xr[i].x, xr[i].y);
                d[1] = f2h2(xr[i].z, xr[i].w);
            }
            if (tid < 32) {
                int idx = 1536 + tid, row = idx >> 3, c4 = idx & 7;
                uint32_t* d = reinterpret_cast<uint32_t*>(xsb + row * 80 + c4 * 8);
                d[0] = f2h2(xr[6].x, xr[6].y);
                d[1] = f2h2(xr[6].z, xr[6].w);
            }
            char* asb = smem + OFF_AS + buf * ABUF_BYTES;
#pragma unroll
            for (int i = 0; i < 2; i++) {
                int idx = i * 256 + tid, row = idx >> 3, c4 = idx & 7;
                uint32_t* d = reinterpret_cast<uint32_t*>(asb + row * 80 + c4 * 8);
                d[0] = f2h2(ar[i].x, ar[i].y);
                d[1] = f2h2(ar[i].z, ar[i].w);
            }
        }

        // ---- issue next chunk's LDGs BEFORE the barrier (xr/ar now dead) ----
        if (ch + 1 < NCH) {
            const float* xc = xb + (ch + 1) * KC;
            const float* ac = Amat + (ch + 1) * KC;
#pragma unroll
            for (int i = 0; i < 6; i++) {
                int idx = i * 256 + tid, row = idx >> 3, c4 = idx & 7;
                xr[i] = *reinterpret_cast<const float4*>(xc + row * C_DIM + c4 * 4);
            }
            if (tid < 32) {
                int idx = 1536 + tid, row = idx >> 3, c4 = idx & 7;
                xr[6] = *reinterpret_cast<const float4*>(xc + row * C_DIM + c4 * 4);
            }
#pragma unroll
            for (int i = 0; i < 2; i++) {
                int idx = i * 256 + tid, row = idx >> 3, c4 = idx & 7;
                ar[i] = *reinterpret_cast<const float4*>(ac + row * C_DIM + c4 * 4);
            }
        }

        // single barrier per chunk: orders STS(buf) before all warps' ldsm(buf);
        // also (via next iteration's barrier) orders mma(buf) before STS(buf)@ch+2
        __syncthreads();

        // ---- mma over buf ----
        {
            const uint32_t asb = sb + OFF_AS + buf * ABUF_BYTES;
            const uint32_t xsb = sb + OFF_XS + buf * XBUF_BYTES;
#pragma unroll
            for (int ks = 0; ks < 2; ks++) {
                const int k0 = ks * 16;
                uint32_t a[4];
                ldsm4(a, asb + (arow * XPITCH + k0 + acolofs) * 2);
#pragma unroll
                for (int g = 0; g < 6; g++) {
                    uint32_t b[4];
                    ldsm4(b, xsb + ((phalf + g * 16 + browofs) * XPITCH + k0 + bcolofs) * 2);
                    mma16816(acc[2 * g], a, &b[0]);
                    mma16816(acc[2 * g + 1], a, &b[2]);
                }
                uint32_t b2[2];
                ldsm2(b2, xsb + ((phalf + 96 + (lane & 7)) * XPITCH + k0 + ((lane & 8) ? 8 : 0)) * 2);
                mma16816(acc[12], a, b2);
            }
        }
    }

    // all mma reads of the last buffers complete per-warp before T store (reg dep);
    // T region is disjoint from X/A buffers, so no cross-warp hazard here.
    {
        char* ts = smem + OFF_TS;
        const int r0 = (wid >> 1) * 16 + lane / 4;
        const int cb = phalf + (lane & 3) * 2;
#pragma unroll
        for (int nt = 0; nt < 13; nt++) {
            int c = cb + nt * 8;
            *reinterpret_cast<uint32_t*>(ts + (r0 * TPITCH + c) * 2) = f2h2(acc[nt][0], acc[nt][1]);
            *reinterpret_cast<uint32_t*>(ts + ((r0 + 8) * TPITCH + c) * 2) = f2h2(acc[nt][2], acc[nt][3]);
        }
    }
    __syncthreads();

    // ---- G2: out[a,h] = sum_p T[a,p] B[p,h], K = 208 ----
    float o[4][4];
#pragma unroll
    for (int i = 0; i < 4; i++) {
        o[i][0] = o[i][1] = o[i][2] = o[i][3] = 0.0f;
    }
    const uint32_t tsb = sb + OFF_TS;
    const uint32_t bsb = sb + OFF_BS;
    const int a2row = (wid >> 1) * 16 + (lane & 15);
    const int a2co = (lane & 16) ? 8 : 0;
    const int hhalf = (wid & 1) * 32;
#pragma unroll
    for (int ks = 0; ks < 13; ks++) {
        const int k0 = ks * 16;
        uint32_t a[4];
        ldsm4(a, tsb + (a2row * TPITCH + k0 + a2co) * 2);
#pragma unroll
        for (int g = 0; g < 2; g++) {
            uint32_t b[4];
            ldsm4(b, bsb + ((hhalf + g * 16 + browofs) * TPITCH + k0 + bcolofs) * 2);
            mma16816(o[2 * g], a, &b[0]);
            mma16816(o[2 * g + 1], a, &b[2]);
        }
    }

    // ---- epilogue ----
    {
        float* ob = out + (size_t)bn * 4096;
        const int r0 = (wid >> 1) * 16 + lane / 4;
        const int cb = hhalf + (lane & 3) * 2;
#pragma unroll
        for (int nt = 0; nt < 4; nt++) {
            int c = cb + nt * 8;
            *reinterpret_cast<float2*>(ob + r0 * 64 + c) = make_float2(o[nt][0], o[nt][1]);
            *reinterpret_cast<float2*>(ob + (r0 + 8) * 64 + c) = make_float2(o[nt][2], o[nt][3]);
        }
    }
}

extern "C" void kernel_launch(void* const* d_in, const int* in_sizes, int n_in,
                              void* d_out, int out_size) {
    int ix = 0, ia = 1, ib = 2;
    for (int i = 0; i < n_in; i++) {
        if (in_sizes[i] == 237244416) ix = i;
        else if (in_sizes[i] == 49152) ia = i;
        else if (in_sizes[i] == 12544) ib = i;
    }
    const float* x = (const float*)d_in[ix];
    const float* A = (const float*)d_in[ia];
    const float* B = (const float*)d_in[ib];
    float* out = (float*)d_out;

    cudaFuncSetAttribute(sepnet_fused_kernel,
                         cudaFuncAttributeMaxDynamicSharedMemorySize, SMEM_BYTES);
    sepnet_fused_kernel<<<1576, 256, SMEM_BYTES>>>(x, A, B, out);
}

// round 8
// speedup vs baseline: 2.2968x; 1.0870x over previous
#include <cuda_runtime.h>
#include <cuda.h>
#include <cuda_fp16.h>
#include <cstdint>

// out[bn] = A @ x[bn]^T @ B.  R8: TMA bulk-tensor loads + mma.sync tf32 (G1) + proven fp16 G2.
// G1: T[a=64, p=208pad] = sum_c A[a,c] x[p,c]  (K=768, 24 chunks of 32, f32 via TMA, tf32 mma)
// G2: out[a,h] = sum_p T[a,p] B[p,h]           (K=208, f16 mma, R7-proven)
#define P_DIM 196
#define C_DIM 768
#define NCH 24
#define PP 208
#define XST_B (PP * 128)              // 26624 X region per stage (f32, SW128)
#define AST_B (64 * 128)              // 8192  A region per stage
#define STG_B (XST_B + AST_B)         // 34816
#define NST 3
#define STAGES_B (NST * STG_B)        // 104448
#define TPITCH 216                    // halves per T/Bs row (R7)
#define OFF_TS 0                      // T aliases stage0/1 (used only after G1)
#define OFF_BS (64 * TPITCH * 2)      // 27648
#define MB_OFF STAGES_B
#define SMEM_ALLOC (STAGES_B + 64 + 1024)
#define TX_BYTES (P_DIM * 128 + AST_B)   // 33280 per stage

#define DEVINL __device__ __forceinline__

__device__ float g_Atf[64 * C_DIM];   // A pre-rounded to tf32 (RN)

DEVINL uint32_t smem_u32(const void* p) {
    uint32_t a;
    asm("{ .reg .u64 t; cvta.to.shared.u64 t, %1; cvt.u32.u64 %0, t; }" : "=r"(a) : "l"(p));
    return a;
}
DEVINL uint32_t f2h2(float lo, float hi) {
    __half2 h = __floats2half2_rn(lo, hi);
    return *reinterpret_cast<uint32_t*>(&h);
}
DEVINL uint32_t lds32(uint32_t addr) {
    uint32_t v;
    asm volatile("ld.shared.b32 %0, [%1];" : "=r"(v) : "r"(addr));
    return v;
}
DEVINL void ldsm4(uint32_t* r, uint32_t addr) {
    asm volatile("ldmatrix.sync.aligned.m8n8.x4.shared.b16 {%0,%1,%2,%3}, [%4];"
                 : "=r"(r[0]), "=r"(r[1]), "=r"(r[2]), "=r"(r[3]) : "r"(addr));
}
DEVINL void mma16816(float* d, const uint32_t* a, const uint32_t* b) {
    asm volatile("mma.sync.aligned.m16n8k16.row.col.f32.f16.f16.f32 "
                 "{%0,%1,%2,%3}, {%4,%5,%6,%7}, {%8,%9}, {%0,%1,%2,%3};"
                 : "+f"(d[0]), "+f"(d[1]), "+f"(d[2]), "+f"(d[3])
                 : "r"(a[0]), "r"(a[1]), "r"(a[2]), "r"(a[3]), "r"(b[0]), "r"(b[1]));
}
DEVINL void mma_tf32(float* d, uint32_t a0, uint32_t a1, uint32_t a2, uint32_t a3,
                     uint32_t b0, uint32_t b1) {
    asm volatile("mma.sync.aligned.m16n8k8.row.col.f32.tf32.tf32.f32 "
                 "{%0,%1,%2,%3}, {%4,%5,%6,%7}, {%8,%9}, {%0,%1,%2,%3};"
                 : "+f"(d[0]), "+f"(d[1]), "+f"(d[2]), "+f"(d[3])
                 : "r"(a0), "r"(a1), "r"(a2), "r"(a3), "r"(b0), "r"(b1));
}

#define MBAR_INIT(a, c) \
    asm volatile("mbarrier.init.shared.b64 [%0], %1;" :: "r"((uint32_t)(a)), "r"((uint32_t)(c)) : "memory")
#define MBAR_EXPECT_TX(a, b) \
    asm volatile("mbarrier.arrive.expect_tx.shared.b64 _, [%0], %1;" :: "r"((uint32_t)(a)), "r"((uint32_t)(b)) : "memory")
#define MBAR_WAIT(a, p) do {                                                              \
    asm volatile("{ .reg .pred P; WL%=:\n\t"                                              \
        "mbarrier.try_wait.parity.acquire.cta.shared::cta.b64 P, [%0], %1, 0x989680;\n\t" \
        "@P bra.uni WD%=;\n\t bra.uni WL%=;\n\t WD%=: }"                                  \
        :: "r"((uint32_t)(a)), "r"((uint32_t)(p)) : "memory");                            \
} while (0)
#define TMA_2D(dst, map, cx, cy, mb) \
    asm volatile("cp.async.bulk.tensor.2d.shared::cta.global.tile.mbarrier::complete_tx::bytes " \
        "[%0], [%1, {%2, %3}], [%4];" \
        :: "r"((uint32_t)(dst)), "l"(map), "r"((int)(cx)), "r"((int)(cy)), "r"((uint32_t)(mb)) : "memory")
#define TMA_3D(dst, map, cx, cy, cz, mb) \
    asm volatile("cp.async.bulk.tensor.3d.shared::cta.global.tile.mbarrier::complete_tx::bytes " \
        "[%0], [%1, {%2, %3, %4}], [%5];" \
        :: "r"((uint32_t)(dst)), "l"(map), "r"((int)(cx)), "r"((int)(cy)), "r"((int)(cz)), "r"((uint32_t)(mb)) : "memory")

__global__ void cvt_A_kernel(const float* __restrict__ A) {
    int i = blockIdx.x * 256 + threadIdx.x;
    if (i < 64 * C_DIM) {
        uint32_t v;
        asm("cvt.rna.tf32.f32 %0, %1;" : "=r"(v) : "f"(A[i]));
        g_Atf[i] = __uint_as_float(v);
    }
}

__global__ void __launch_bounds__(256, 2) sepnet_tma_kernel(
    const float* __restrict__ Bmat, float* __restrict__ out,
    const __grid_constant__ CUtensorMap tmX,
    const __grid_constant__ CUtensorMap tmA)
{
    extern __shared__ char smem_raw[];
    const uint32_t sb = (smem_u32(smem_raw) + 1023) & ~1023u;  // 1024B align for SW128
    const int tid = threadIdx.x;
    const int wid = tid >> 5;
    const int lane = tid & 31;
    const int bn = blockIdx.x;

    if (tid == 0)
        for (int s = 0; s < NST; s++) MBAR_INIT(sb + MB_OFF + 8 * s, 1);
    // zero X pad rows (196..207) in all stages
    for (int i = tid; i < NST * 384; i += 256) {
        int s = i / 384, w = i % 384;
        asm volatile("st.shared.b32 [%0], %1;"
            :: "r"(sb + s * STG_B + P_DIM * 128 + w * 4), "r"(0u) : "memory");
    }
    __syncthreads();
    if (tid == 0) {
#pragma unroll
        for (int pre = 0; pre < 2; pre++) {
            uint32_t mb = sb + MB_OFF + 8 * pre;
            MBAR_EXPECT_TX(mb, TX_BYTES);
            TMA_3D(sb + pre * STG_B, &tmX, pre * 32, 0, bn, mb);
            TMA_2D(sb + pre * STG_B + XST_B, &tmA, pre * 32, 0, mb);
        }
    }

    // ---- G1: tf32, warp = (abase: 16 a-rows) x (pbase: 104 p-cols, 13 n8-tiles) ----
    float acc[13][4];
#pragma unroll
    for (int i = 0; i < 13; i++)
        acc[i][0] = acc[i][1] = acc[i][2] = acc[i][3] = 0.0f;

    const int abase = (wid >> 1) * 16;
    const int pbase = (wid & 1) * 104;
    const uint32_t word = (lane & 3) * 4;
    const uint32_t sxor = lane >> 2;
    const uint32_t arow_off = (uint32_t)(abase + (lane >> 2)) * 128 + word;   // within A region
    const uint32_t prow_off = (uint32_t)(pbase + (lane >> 2)) * 128 + word;   // within X region

    for (int ch = 0; ch < NCH; ch++) {
        const int s = ch % 3;
        const uint32_t ph = (uint32_t)((ch / 3) & 1);
        __syncthreads();   // all warps done with mma(ch-1) -> stage (ch-1)%3 is free
        if (tid == 0 && ch + 2 < NCH) {
            int s2 = (ch + 2) % 3;
            uint32_t mb = sb + MB_OFF + 8 * s2;
            MBAR_EXPECT_TX(mb, TX_BYTES);
            TMA_3D(sb + s2 * STG_B, &tmX, (ch + 2) * 32, 0, bn, mb);
            TMA_2D(sb + s2 * STG_B + XST_B, &tmA, (ch + 2) * 32, 0, mb);
        }
        MBAR_WAIT(sb + MB_OFF + 8 * s, ph);

        const uint32_t Ab = sb + s * STG_B + XST_B + arow_off;
        const uint32_t Pb = sb + s * STG_B + prow_off;
#pragma unroll
        for (int ks = 0; ks < 4; ks++) {
            const uint32_t c0 = ((uint32_t)(2 * ks) ^ sxor) << 4;
            const uint32_t c1 = ((uint32_t)(2 * ks + 1) ^ sxor) << 4;
            uint32_t a0 = lds32(Ab + c0);
            uint32_t a2 = lds32(Ab + c1);
            uint32_t a1 = lds32(Ab + 1024 + c0);
            uint32_t a3 = lds32(Ab + 1024 + c1);
#pragma unroll
            for (int t = 0; t < 13; t++) {
                uint32_t b0 = lds32(Pb + t * 1024 + c0);
                uint32_t b1 = lds32(Pb + t * 1024 + c1);
                mma_tf32(acc[t], a0, a1, a2, a3, b0, b1);
            }
        }
    }

    // ---- T (f16) into alias region (stages 0/1; stage 2 still in use only by mma(23)) ----
    {
        const int r0 = abase + lane / 4;
        const int cb = pbase + (lane & 3) * 2;
#pragma unroll
        for (int nt = 0; nt < 13; nt++) {
            int c = cb + nt * 8;
            asm volatile("st.shared.b32 [%0], %1;"
                :: "r"(sb + OFF_TS + (r0 * TPITCH + c) * 2), "r"(f2h2(acc[nt][0], acc[nt][1])) : "memory");
            asm volatile("st.shared.b32 [%0], %1;"
                :: "r"(sb + OFF_TS + ((r0 + 8) * TPITCH + c) * 2), "r"(f2h2(acc[nt][2], acc[nt][3])) : "memory");
        }
    }
    // Bs[h][p] f16, pads zero
    for (int i = tid; i < 64 * PP; i += 256) {
        int p = i >> 6, h = i & 63;
        float v = (p < P_DIM) ? Bmat[p * 64 + h] : 0.0f;
        unsigned short hb = __half_as_ushort(__float2half_rn(v));
        asm volatile("st.shared.b16 [%0], %1;"
            :: "r"(sb + OFF_BS + (h * TPITCH + p) * 2), "h"(hb) : "memory");
    }
    __syncthreads();

    // ---- G2 (R7-proven): out[a,h] = sum_p T[a,p] Bs[h,p], K = 208, fp16 ----
    float o[4][4];
#pragma unroll
    for (int i = 0; i < 4; i++)
        o[i][0] = o[i][1] = o[i][2] = o[i][3] = 0.0f;
    const uint32_t tsb = sb + OFF_TS;
    const uint32_t bsb = sb + OFF_BS;
    const int a2row = (wid >> 1) * 16 + (lane & 15);
    const int a2co = (lane & 16) ? 8 : 0;
    const int hhalf = (wid & 1) * 32;
    const int browofs = (lane & 7) + ((lane & 16) >> 1);
    const int bcolofs = ((lane >> 3) & 1) * 8;
#pragma unroll
    for (int ks = 0; ks < 13; ks++) {
        const int k0 = ks * 16;
        uint32_t a[4];
        ldsm4(a, tsb + (a2row * TPITCH + k0 + a2co) * 2);
#pragma unroll
        for (int g = 0; g < 2; g++) {
            uint32_t b[4];
            ldsm4(b, bsb + ((hhalf + g * 16 + browofs) * TPITCH + k0 + bcolofs) * 2);
            mma16816(o[2 * g], a, &b[0]);
            mma16816(o[2 * g + 1], a, &b[2]);
        }
    }
    {
        float* ob = out + (size_t)bn * 4096;
        const int r0 = (wid >> 1) * 16 + lane / 4;
        const int cb = hhalf + (lane & 3) * 2;
#pragma unroll
        for (int nt = 0; nt < 4; nt++) {
            int c = cb + nt * 8;
            *reinterpret_cast<float2*>(ob + r0 * 64 + c) = make_float2(o[nt][0], o[nt][1]);
            *reinterpret_cast<float2*>(ob + (r0 + 8) * 64 + c) = make_float2(o[nt][2], o[nt][3]);
        }
    }
}

extern "C" void kernel_launch(void* const* d_in, const int* in_sizes, int n_in,
                              void* d_out, int out_size) {
    int ix = 0, ia = 1, ib = 2;
    for (int i = 0; i < n_in; i++) {
        if (in_sizes[i] == 237244416) ix = i;
        else if (in_sizes[i] == 49152) ia = i;
        else if (in_sizes[i] == 12544) ib = i;
    }
    void* xp = d_in[ix];
    const float* A = (const float*)d_in[ia];
    const float* B = (const float*)d_in[ib];
    float* out = (float*)d_out;

    void* atf_ptr = nullptr;
    cudaGetSymbolAddress(&atf_ptr, g_Atf);

    typedef CUresult (CUDAAPI * EncFn)(
        CUtensorMap*, CUtensorMapDataType, cuuint32_t, void*,
        const cuuint64_t*, const cuuint64_t*, const cuuint32_t*, const cuuint32_t*,
        CUtensorMapInterleave, CUtensorMapSwizzle, CUtensorMapL2promotion, CUtensorMapFloatOOBfill);
    void* fnp = nullptr;
    cudaDriverEntryPointQueryResult qr;
    cudaGetDriverEntryPointByVersion("cuTensorMapEncodeTiled", &fnp, 12000,
                                     cudaEnableDefault, &qr);
    EncFn enc = (EncFn)fnp;

    CUtensorMap tmX, tmA;
    {
        cuuint64_t dims[3] = { (cuuint64_t)C_DIM, (cuuint64_t)P_DIM, 1576 };
        cuuint64_t strides[2] = { (cuuint64_t)C_DIM * 4, (cuuint64_t)P_DIM * C_DIM * 4 };
        cuuint32_t box[3] = { 32, (cuuint32_t)P_DIM, 1 };
        cuuint32_t es[3] = { 1, 1, 1 };
        enc(&tmX, CU_TENSOR_MAP_DATA_TYPE_FLOAT32, 3, xp, dims, strides, box, es,
            CU_TENSOR_MAP_INTERLEAVE_NONE, CU_TENSOR_MAP_SWIZZLE_128B,
            CU_TENSOR_MAP_L2_PROMOTION_L2_128B, CU_TENSOR_MAP_FLOAT_OOB_FILL_NONE);
    }
    {
        cuuint64_t dims[2] = { (cuuint64_t)C_DIM, 64 };
        cuuint64_t strides[1] = { (cuuint64_t)C_DIM * 4 };
        cuuint32_t box[2] = { 32, 64 };
        cuuint32_t es[2] = { 1, 1 };
        enc(&tmA, CU_TENSOR_MAP_DATA_TYPE_FLOAT32, 2, atf_ptr, dims, strides, box, es,
            CU_TENSOR_MAP_INTERLEAVE_NONE, CU_TENSOR_MAP_SWIZZLE_128B,
            CU_TENSOR_MAP_L2_PROMOTION_L2_128B, CU_TENSOR_MAP_FLOAT_OOB_FILL_NONE);
    }

    cvt_A_kernel<<<(64 * C_DIM + 255) / 256, 256>>>(A);
    cudaFuncSetAttribute(sepnet_tma_kernel,
                         cudaFuncAttributeMaxDynamicSharedMemorySize, SMEM_ALLOC);
    sepnet_tma_kernel<<<1576, 256, SMEM_ALLOC>>>(B, out, tmX, tmA);
}

// round 9
// speedup vs baseline: 2.3930x; 1.0419x over previous
#include <cuda_runtime.h>
#include <cuda.h>
#include <cuda_fp16.h>
#include <cstdint>

// out[bn] = A @ x[bn]^T @ B.  R9 = R8 (TMA + tf32 G1 + fp16 G2) retiled 2a x 4p
// to cut SMEM crossbar traffic 27% (L1 was the 70.9% leader).
// G1: T[a=64, p=224pad] = sum_c A[a,c] x[p,c]  (K=768, 24 chunks of 32)
// G2: out[a,h] = sum_p T[a,p] B[p,h]           (K=224)
#define P_DIM 196
#define C_DIM 768
#define NCH 24
#define PP 224
#define XST_B (PP * 128)              // 28672 X region per stage (f32, SW128)
#define AST_B (64 * 128)              // 8192  A region per stage
#define STG_B (XST_B + AST_B)         // 36864
#define NST 3
#define STAGES_B (NST * STG_B)        // 110592
#define TPITCH 232                    // halves per T/Bs row
#define OFF_TS 0
#define OFF_BS (64 * TPITCH * 2)      // 29696
#define MB_OFF STAGES_B
#define SMEM_ALLOC (STAGES_B + 64 + 1024)
#define TX_BYTES (P_DIM * 128 + AST_B)   // 33280 per stage

#define DEVINL __device__ __forceinline__

__device__ float g_Atf[64 * C_DIM];   // A pre-rounded to tf32 (RN)

DEVINL uint32_t smem_u32(const void* p) {
    uint32_t a;
    asm("{ .reg .u64 t; cvta.to.shared.u64 t, %1; cvt.u32.u64 %0, t; }" : "=r"(a) : "l"(p));
    return a;
}
DEVINL uint32_t f2h2(float lo, float hi) {
    __half2 h = __floats2half2_rn(lo, hi);
    return *reinterpret_cast<uint32_t*>(&h);
}
DEVINL uint32_t lds32(uint32_t addr) {
    uint32_t v;
    asm volatile("ld.shared.b32 %0, [%1];" : "=r"(v) : "r"(addr));
    return v;
}
DEVINL void ldsm4(uint32_t* r, uint32_t addr) {
    asm volatile("ldmatrix.sync.aligned.m8n8.x4.shared.b16 {%0,%1,%2,%3}, [%4];"
                 : "=r"(r[0]), "=r"(r[1]), "=r"(r[2]), "=r"(r[3]) : "r"(addr));
}
DEVINL void mma16816(float* d, const uint32_t* a, const uint32_t* b) {
    asm volatile("mma.sync.aligned.m16n8k16.row.col.f32.f16.f16.f32 "
                 "{%0,%1,%2,%3}, {%4,%5,%6,%7}, {%8,%9}, {%0,%1,%2,%3};"
                 : "+f"(d[0]), "+f"(d[1]), "+f"(d[2]), "+f"(d[3])
                 : "r"(a[0]), "r"(a[1]), "r"(a[2]), "r"(a[3]), "r"(b[0]), "r"(b[1]));
}
DEVINL void mma_tf32(float* d, uint32_t a0, uint32_t a1, uint32_t a2, uint32_t a3,
                     uint32_t b0, uint32_t b1) {
    asm volatile("mma.sync.aligned.m16n8k8.row.col.f32.tf32.tf32.f32 "
                 "{%0,%1,%2,%3}, {%4,%5,%6,%7}, {%8,%9}, {%0,%1,%2,%3};"
                 : "+f"(d[0]), "+f"(d[1]), "+f"(d[2]), "+f"(d[3])
                 : "r"(a0), "r"(a1), "r"(a2), "r"(a3), "r"(b0), "r"(b1));
}

#define MBAR_INIT(a, c) \
    asm volatile("mbarrier.init.shared.b64 [%0], %1;" :: "r"((uint32_t)(a)), "r"((uint32_t)(c)) : "memory")
#define MBAR_EXPECT_TX(a, b) \
    asm volatile("mbarrier.arrive.expect_tx.shared.b64 _, [%0], %1;" :: "r"((uint32_t)(a)), "r"((uint32_t)(b)) : "memory")
#define MBAR_WAIT(a, p) do {                                                              \
    asm volatile("{ .reg .pred P; WL%=:\n\t"                                              \
        "mbarrier.try_wait.parity.acquire.cta.shared::cta.b64 P, [%0], %1, 0x989680;\n\t" \
        "@P bra.uni WD%=;\n\t bra.uni WL%=;\n\t WD%=: }"                                  \
        :: "r"((uint32_t)(a)), "r"((uint32_t)(p)) : "memory");                            \
} while (0)
#define TMA_2D(dst, map, cx, cy, mb) \
    asm volatile("cp.async.bulk.tensor.2d.shared::cta.global.tile.mbarrier::complete_tx::bytes " \
        "[%0], [%1, {%2, %3}], [%4];" \
        :: "r"((uint32_t)(dst)), "l"(map), "r"((int)(cx)), "r"((int)(cy)), "r"((uint32_t)(mb)) : "memory")
#define TMA_3D(dst, map, cx, cy, cz, mb) \
    asm volatile("cp.async.bulk.tensor.3d.shared::cta.global.tile.mbarrier::complete_tx::bytes " \
        "[%0], [%1, {%2, %3, %4}], [%5];" \
        :: "r"((uint32_t)(dst)), "l"(map), "r"((int)(cx)), "r"((int)(cy)), "r"((int)(cz)), "r"((uint32_t)(mb)) : "memory")

__global__ void cvt_A_kernel(const float* __restrict__ A) {
    int i = blockIdx.x * 256 + threadIdx.x;
    if (i < 64 * C_DIM) {
        uint32_t v;
        asm("cvt.rna.tf32.f32 %0, %1;" : "=r"(v) : "f"(A[i]));
        g_Atf[i] = __uint_as_float(v);
    }
}

__global__ void __launch_bounds__(256, 2) sepnet_tma_kernel(
    const float* __restrict__ Bmat, float* __restrict__ out,
    const __grid_constant__ CUtensorMap tmX,
    const __grid_constant__ CUtensorMap tmA)
{
    extern __shared__ char smem_raw[];
    const uint32_t sb = (smem_u32(smem_raw) + 1023) & ~1023u;
    const int tid = threadIdx.x;
    const int wid = tid >> 5;
    const int lane = tid & 31;
    const int bn = blockIdx.x;

    if (tid == 0)
        for (int s = 0; s < NST; s++) MBAR_INIT(sb + MB_OFF + 8 * s, 1);
    // zero X pad rows (196..223) in all stages: 28 rows * 32 words * 3 stages
    for (int i = tid; i < NST * 896; i += 256) {
        int s = i / 896, w = i % 896;
        asm volatile("st.shared.b32 [%0], %1;"
            :: "r"(sb + s * STG_B + P_DIM * 128 + w * 4), "r"(0u) : "memory");
    }
    __syncthreads();
    if (tid == 0) {
#pragma unroll
        for (int pre = 0; pre < 2; pre++) {
            uint32_t mb = sb + MB_OFF + 8 * pre;
            MBAR_EXPECT_TX(mb, TX_BYTES);
            TMA_3D(sb + pre * STG_B, &tmX, pre * 32, 0, bn, mb);
            TMA_2D(sb + pre * STG_B + XST_B, &tmA, pre * 32, 0, mb);
        }
    }

    // ---- G1: tf32, warp = (agrp: 32 a-rows) x (pgrp: 56 p-cols, 7 n8-tiles) ----
    float acc[2][7][4];
#pragma unroll
    for (int m = 0; m < 2; m++)
#pragma unroll
        for (int t = 0; t < 7; t++)
            acc[m][t][0] = acc[m][t][1] = acc[m][t][2] = acc[m][t][3] = 0.0f;

    const int abase = (wid & 1) * 32;
    const int pbase = (wid >> 1) * 56;
    const uint32_t word = (lane & 3) * 4;
    const uint32_t sxor = lane >> 2;
    const uint32_t arow_off = (uint32_t)(abase + (lane >> 2)) * 128 + word;
    const uint32_t prow_off = (uint32_t)(pbase + (lane >> 2)) * 128 + word;

    for (int ch = 0; ch < NCH; ch++) {
        const int s = ch % 3;
        const uint32_t ph = (uint32_t)((ch / 3) & 1);
        __syncthreads();
        if (tid == 0 && ch + 2 < NCH) {
            int s2 = (ch + 2) % 3;
            uint32_t mb = sb + MB_OFF + 8 * s2;
            MBAR_EXPECT_TX(mb, TX_BYTES);
            TMA_3D(sb + s2 * STG_B, &tmX, (ch + 2) * 32, 0, bn, mb);
            TMA_2D(sb + s2 * STG_B + XST_B, &tmA, (ch + 2) * 32, 0, mb);
        }
        MBAR_WAIT(sb + MB_OFF + 8 * s, ph);

        const uint32_t Ab = sb + s * STG_B + XST_B + arow_off;
        const uint32_t Pb = sb + s * STG_B + prow_off;
#pragma unroll
        for (int ks = 0; ks < 4; ks++) {
            const uint32_t c0 = ((uint32_t)(2 * ks) ^ sxor) << 4;
            const uint32_t c1 = ((uint32_t)(2 * ks + 1) ^ sxor) << 4;
            uint32_t a00 = lds32(Ab + c0);
            uint32_t a02 = lds32(Ab + c1);
            uint32_t a01 = lds32(Ab + 1024 + c0);
            uint32_t a03 = lds32(Ab + 1024 + c1);
            uint32_t a10 = lds32(Ab + 2048 + c0);
            uint32_t a12 = lds32(Ab + 2048 + c1);
            uint32_t a11 = lds32(Ab + 3072 + c0);
            uint32_t a13 = lds32(Ab + 3072 + c1);
#pragma unroll
            for (int t = 0; t < 7; t++) {
                uint32_t b0 = lds32(Pb + t * 1024 + c0);
                uint32_t b1 = lds32(Pb + t * 1024 + c1);
                mma_tf32(acc[0][t], a00, a01, a02, a03, b0, b1);
                mma_tf32(acc[1][t], a10, a11, a12, a13, b0, b1);
            }
        }
    }

    // ---- T (f16) into alias region (stages 0/1; only stage 2 still being read) ----
    {
        const int cb = pbase + (lane & 3) * 2;
#pragma unroll
        for (int m = 0; m < 2; m++) {
            const int r0 = abase + m * 16 + (lane >> 2);
#pragma unroll
            for (int t = 0; t < 7; t++) {
                int c = cb + t * 8;
                asm volatile("st.shared.b32 [%0], %1;"
                    :: "r"(sb + OFF_TS + (r0 * TPITCH + c) * 2), "r"(f2h2(acc[m][t][0], acc[m][t][1])) : "memory");
                asm volatile("st.shared.b32 [%0], %1;"
                    :: "r"(sb + OFF_TS + ((r0 + 8) * TPITCH + c) * 2), "r"(f2h2(acc[m][t][2], acc[m][t][3])) : "memory");
            }
        }
    }
    // Bs[h][p] f16, pads zero
    for (int i = tid; i < 64 * PP; i += 256) {
        int p = i >> 6, h = i & 63;
        float v = (p < P_DIM) ? Bmat[p * 64 + h] : 0.0f;
        unsigned short hb = __half_as_ushort(__float2half_rn(v));
        asm volatile("st.shared.b16 [%0], %1;"
            :: "r"(sb + OFF_BS + (h * TPITCH + p) * 2), "h"(hb) : "memory");
    }
    __syncthreads();

    // ---- G2: out[a,h] = sum_p T[a,p] Bs[h,p], K = 224, fp16 ----
    float o[4][4];
#pragma unroll
    for (int i = 0; i < 4; i++)
        o[i][0] = o[i][1] = o[i][2] = o[i][3] = 0.0f;
    const uint32_t tsb = sb + OFF_TS;
    const uint32_t bsb = sb + OFF_BS;
    const int a2row = (wid >> 1) * 16 + (lane & 15);
    const int a2co = (lane & 16) ? 8 : 0;
    const int hhalf = (wid & 1) * 32;
    const int browofs = (lane & 7) + ((lane & 16) >> 1);
    const int bcolofs = ((lane >> 3) & 1) * 8;
#pragma unroll
    for (int ks = 0; ks < 14; ks++) {
        const int k0 = ks * 16;
        uint32_t a[4];
        ldsm4(a, tsb + (a2row * TPITCH + k0 + a2co) * 2);
#pragma unroll
        for (int g = 0; g < 2; g++) {
            uint32_t b[4];
            ldsm4(b, bsb + ((hhalf + g * 16 + browofs) * TPITCH + k0 + bcolofs) * 2);
            mma16816(o[2 * g], a, &b[0]);
            mma16816(o[2 * g + 1], a, &b[2]);
        }
    }
    {
        float* ob = out + (size_t)bn * 4096;
        const int r0 = (wid >> 1) * 16 + lane / 4;
        const int cb = hhalf + (lane & 3) * 2;
#pragma unroll
        for (int nt = 0; nt < 4; nt++) {
            int c = cb + nt * 8;
            *reinterpret_cast<float2*>(ob + r0 * 64 + c) = make_float2(o[nt][0], o[nt][1]);
            *reinterpret_cast<float2*>(ob + (r0 + 8) * 64 + c) = make_float2(o[nt][2], o[nt][3]);
        }
    }
}

extern "C" void kernel_launch(void* const* d_in, const int* in_sizes, int n_in,
                              void* d_out, int out_size) {
    int ix = 0, ia = 1, ib = 2;
    for (int i = 0; i < n_in; i++) {
        if (in_sizes[i] == 237244416) ix = i;
        else if (in_sizes[i] == 49152) ia = i;
        else if (in_sizes[i] == 12544) ib = i;
    }
    void* xp = d_in[ix];
    const float* A = (const float*)d_in[ia];
    const float* B = (const float*)d_in[ib];
    float* out = (float*)d_out;

    void* atf_ptr = nullptr;
    cudaGetSymbolAddress(&atf_ptr, g_Atf);

    typedef CUresult (CUDAAPI * EncFn)(
        CUtensorMap*, CUtensorMapDataType, cuuint32_t, void*,
        const cuuint64_t*, const cuuint64_t*, const cuuint32_t*, const cuuint32_t*,
        CUtensorMapInterleave, CUtensorMapSwizzle, CUtensorMapL2promotion, CUtensorMapFloatOOBfill);
    void* fnp = nullptr;
    cudaDriverEntryPointQueryResult qr;
    cudaGetDriverEntryPointByVersion("cuTensorMapEncodeTiled", &fnp, 12000,
                                     cudaEnableDefault, &qr);
    EncFn enc = (EncFn)fnp;

    CUtensorMap tmX, tmA;
    {
        cuuint64_t dims[3] = { (cuuint64_t)C_DIM, (cuuint64_t)P_DIM, 1576 };
        cuuint64_t strides[2] = { (cuuint64_t)C_DIM * 4, (cuuint64_t)P_DIM * C_DIM * 4 };
        cuuint32_t box[3] = { 32, (cuuint32_t)P_DIM, 1 };
        cuuint32_t es[3] = { 1, 1, 1 };
        enc(&tmX, CU_TENSOR_MAP_DATA_TYPE_FLOAT32, 3, xp, dims, strides, box, es,
            CU_TENSOR_MAP_INTERLEAVE_NONE, CU_TENSOR_MAP_SWIZZLE_128B,
            CU_TENSOR_MAP_L2_PROMOTION_L2_128B, CU_TENSOR_MAP_FLOAT_OOB_FILL_NONE);
    }
    {
        cuuint64_t dims[2] = { (cuuint64_t)C_DIM, 64 };
        cuuint64_t strides[1] = { (cuuint64_t)C_DIM * 4 };
        cuuint32_t box[2] = { 32, 64 };
        cuuint32_t es[2] = { 1, 1 };
        enc(&tmA, CU_TENSOR_MAP_DATA_TYPE_FLOAT32, 2, atf_ptr, dims, strides, box, es,
            CU_TENSOR_MAP_INTERLEAVE_NONE, CU_TENSOR_MAP_SWIZZLE_128B,
            CU_TENSOR_MAP_L2_PROMOTION_L2_128B, CU_TENSOR_MAP_FLOAT_OOB_FILL_NONE);
    }

    cvt_A_kernel<<<(64 * C_DIM + 255) / 256, 256>>>(A);
    cudaFuncSetAttribute(sepnet_tma_kernel,
                         cudaFuncAttributeMaxDynamicSharedMemorySize, SMEM_ALLOC);
    sepnet_tma_kernel<<<1576, 256, SMEM_ALLOC>>>(B, out, tmX, tmA);
}